// round 15
// baseline (speedup 1.0000x reference)
#include <cuda_runtime.h>

// ReactDiffDynamics: per batch b (64), channels U,V of 512x512 fp32 (periodic):
//   dUdt = a*lap(U) + U - U^3 - k - V
//   dVdt = b*lap(V) + U - V
// lap = 5-point periodic stencil / dx^2, dx = 0.06451612903.
//
// R15: last untried mechanism -- native 256-bit memory ops (sm_103 supports
// ld/st .v8.b32). One thread owns an 8-float group and marches RPT=4 rows.
// vs R9 (128-bit): half the LDG/STG instruction count, 1024 B/warp per
// instruction (8 L2 sectors per LTS wavefront). vs R8 (2x128-bit, 96 regs,
// occ 26%): v8 keeps the live set at 6 rows x 8 floats = 48 data regs;
// launch_bounds(256,4) caps at 64 regs -> 4 blocks/SM.

#define RD_W  512
#define RD_HW (512 * 512)
#define RPT   4

struct F8 { float4 a, b; };

__device__ __forceinline__ F8 ld_v8(const float* p) {
    F8 v;
    asm volatile("ld.global.nc.v8.b32 {%0,%1,%2,%3,%4,%5,%6,%7}, [%8];"
                 : "=f"(v.a.x), "=f"(v.a.y), "=f"(v.a.z), "=f"(v.a.w),
                   "=f"(v.b.x), "=f"(v.b.y), "=f"(v.b.z), "=f"(v.b.w)
                 : "l"(p));
    return v;
}

__device__ __forceinline__ void st_v8_cs(float* p, const F8& v) {
    asm volatile("st.global.cs.v8.b32 [%0], {%1,%2,%3,%4,%5,%6,%7,%8};"
                 :: "l"(p),
                    "f"(v.a.x), "f"(v.a.y), "f"(v.a.z), "f"(v.a.w),
                    "f"(v.b.x), "f"(v.b.y), "f"(v.b.z), "f"(v.b.w)
                 : "memory");
}

__global__ __launch_bounds__(256, 4) void react_diff_kernel(
    const float* __restrict__ x,
    const float* __restrict__ params,
    float* __restrict__ out)
{
    const float inv_dx2 = 1.0f / (0.06451612903f * 0.06451612903f); // 240.25

    int t    = blockIdx.x * blockDim.x + threadIdx.x; // 0 .. 2^19-1
    int xg   = t & 63;            // 8-float group within row (512/8 = 64)
    int tile = (t >> 6) & 127;    // 4-row tile index (512/4 = 128)
    int b    = t >> 13;           // batch
    int lane = threadIdx.x & 31;

    const float* Ubase = x + (size_t)b * 2 * RD_HW;
    const float* Vbase = Ubase + RD_HW;
    float* OU = out + (size_t)b * 2 * RD_HW;
    float* OV = OU + RD_HW;

    float pa = __ldg(&params[b * 3 + 0]);
    float pb = __ldg(&params[b * 3 + 1]);
    float pk = __ldg(&params[b * 3 + 2]);

    int y0 = tile * RPT;
    int x0 = xg << 3;
    int xl = (x0 - 1) & 511;
    int xr = (x0 + 8) & 511;

    #define LDU(y) ld_v8(Ubase + (size_t)(y) * RD_W + x0)
    #define LDV(y) ld_v8(Vbase + (size_t)(y) * RD_W + x0)

    F8 Uu = LDU((y0 - 1) & 511);
    F8 Uc = LDU(y0);
    F8 Vu = LDV((y0 - 1) & 511);
    F8 Vc = LDV(y0);

    #pragma unroll
    for (int r = 0; r < RPT; r++) {
        int y = y0 + r;
        int yd = (y + 1) & 511;
        F8 Ud = LDU(yd);
        F8 Vd = LDV(yd);

        // horizontal neighbors via shuffle; warp-edge lanes load scalar
        float Ul = __shfl_up_sync(0xFFFFFFFFu, Uc.b.w, 1);
        float Vl = __shfl_up_sync(0xFFFFFFFFu, Vc.b.w, 1);
        float Ur = __shfl_down_sync(0xFFFFFFFFu, Uc.a.x, 1);
        float Vr = __shfl_down_sync(0xFFFFFFFFu, Vc.a.x, 1);
        if (lane == 0) {
            Ul = Ubase[(size_t)y * RD_W + xl];
            Vl = Vbase[(size_t)y * RD_W + xl];
        }
        if (lane == 31) {
            Ur = Ubase[(size_t)y * RD_W + xr];
            Vr = Vbase[(size_t)y * RD_W + xr];
        }

        F8 dU, dV;
        // U channel: lap + pointwise
        {
            float4 l0, l1;
            l0.x = (Ul     + Uc.a.y + Uu.a.x + Ud.a.x - 4.0f * Uc.a.x) * inv_dx2;
            l0.y = (Uc.a.x + Uc.a.z + Uu.a.y + Ud.a.y - 4.0f * Uc.a.y) * inv_dx2;
            l0.z = (Uc.a.y + Uc.a.w + Uu.a.z + Ud.a.z - 4.0f * Uc.a.z) * inv_dx2;
            l0.w = (Uc.a.z + Uc.b.x + Uu.a.w + Ud.a.w - 4.0f * Uc.a.w) * inv_dx2;
            l1.x = (Uc.a.w + Uc.b.y + Uu.b.x + Ud.b.x - 4.0f * Uc.b.x) * inv_dx2;
            l1.y = (Uc.b.x + Uc.b.z + Uu.b.y + Ud.b.y - 4.0f * Uc.b.y) * inv_dx2;
            l1.z = (Uc.b.y + Uc.b.w + Uu.b.z + Ud.b.z - 4.0f * Uc.b.z) * inv_dx2;
            l1.w = (Uc.b.z + Ur     + Uu.b.w + Ud.b.w - 4.0f * Uc.b.w) * inv_dx2;

            dU.a.x = pa * l0.x + Uc.a.x - Uc.a.x * Uc.a.x * Uc.a.x - pk - Vc.a.x;
            dU.a.y = pa * l0.y + Uc.a.y - Uc.a.y * Uc.a.y * Uc.a.y - pk - Vc.a.y;
            dU.a.z = pa * l0.z + Uc.a.z - Uc.a.z * Uc.a.z * Uc.a.z - pk - Vc.a.z;
            dU.a.w = pa * l0.w + Uc.a.w - Uc.a.w * Uc.a.w * Uc.a.w - pk - Vc.a.w;
            dU.b.x = pa * l1.x + Uc.b.x - Uc.b.x * Uc.b.x * Uc.b.x - pk - Vc.b.x;
            dU.b.y = pa * l1.y + Uc.b.y - Uc.b.y * Uc.b.y * Uc.b.y - pk - Vc.b.y;
            dU.b.z = pa * l1.z + Uc.b.z - Uc.b.z * Uc.b.z * Uc.b.z - pk - Vc.b.z;
            dU.b.w = pa * l1.w + Uc.b.w - Uc.b.w * Uc.b.w * Uc.b.w - pk - Vc.b.w;
        }
        // V channel
        {
            float4 l0, l1;
            l0.x = (Vl     + Vc.a.y + Vu.a.x + Vd.a.x - 4.0f * Vc.a.x) * inv_dx2;
            l0.y = (Vc.a.x + Vc.a.z + Vu.a.y + Vd.a.y - 4.0f * Vc.a.y) * inv_dx2;
            l0.z = (Vc.a.y + Vc.a.w + Vu.a.z + Vd.a.z - 4.0f * Vc.a.z) * inv_dx2;
            l0.w = (Vc.a.z + Vc.b.x + Vu.a.w + Vd.a.w - 4.0f * Vc.a.w) * inv_dx2;
            l1.x = (Vc.a.w + Vc.b.y + Vu.b.x + Vd.b.x - 4.0f * Vc.b.x) * inv_dx2;
            l1.y = (Vc.b.x + Vc.b.z + Vu.b.y + Vd.b.y - 4.0f * Vc.b.y) * inv_dx2;
            l1.z = (Vc.b.y + Vc.b.w + Vu.b.z + Vd.b.z - 4.0f * Vc.b.z) * inv_dx2;
            l1.w = (Vc.b.z + Vr     + Vu.b.w + Vd.b.w - 4.0f * Vc.b.w) * inv_dx2;

            dV.a.x = pb * l0.x + Uc.a.x - Vc.a.x;
            dV.a.y = pb * l0.y + Uc.a.y - Vc.a.y;
            dV.a.z = pb * l0.z + Uc.a.z - Vc.a.z;
            dV.a.w = pb * l0.w + Uc.a.w - Vc.a.w;
            dV.b.x = pb * l1.x + Uc.b.x - Vc.b.x;
            dV.b.y = pb * l1.y + Uc.b.y - Vc.b.y;
            dV.b.z = pb * l1.z + Uc.b.z - Vc.b.z;
            dV.b.w = pb * l1.w + Uc.b.w - Vc.b.w;
        }

        st_v8_cs(OU + (size_t)y * RD_W + x0, dU);
        st_v8_cs(OV + (size_t)y * RD_W + x0, dV);

        // rotate rows
        Uu = Uc; Uc = Ud;
        Vu = Vc; Vc = Vd;
    }
    #undef LDU
    #undef LDV
}

extern "C" void kernel_launch(void* const* d_in, const int* in_sizes, int n_in,
                              void* d_out, int out_size)
{
    const float* x      = (const float*)d_in[1];
    const float* params = (const float*)d_in[2];
    float* out          = (float*)d_out;

    // 64 batches * 128 row-tiles * 64 x8-groups = 2^19 threads
    const int threads = 256;
    const int blocks  = (64 * 128 * 64) / threads; // 2048
    react_diff_kernel<<<blocks, threads>>>(x, params, out);
}

// round 16
// speedup vs baseline: 1.0618x; 1.0618x over previous
#include <cuda_runtime.h>

// ReactDiffDynamics: per batch b (64), channels U,V of 512x512 fp32 (periodic):
//   dUdt = a*lap(U) + U - U^3 - k - V
//   dVdt = b*lap(V) + U - V
// lap = 5-point periodic stencil / dx^2, dx = 0.06451612903.
//
// FINAL (= R9, the measured optimum across 15 rounds).
// HBM-floored at ~214 MB/replay at ~5.6-5.7 TB/s. DRAM-efficiency peak of the
// measured occupancy curve (26%->64.8, 40%->70.5, 52%->71.9, 63%->70.4,
// 84%->68.7) and of the access-width sweep (128b > 256b ~ 2x128b > scalar).
// Design: one thread owns one float4 group and marches RPT=4 rows, keeping
// up/center rows of both channels in registers; horizontal neighbors via warp
// shuffle (scalar loads only at warp edges); streaming stores;
// launch_bounds(256,5) -> 48 regs, 5 blocks/SM.
// L2 policy hints (evict_last/fractional/pinning/demotion) all tested:
// inert or harmful without a persisting-L2 carveout (forbidden by harness).

#define RD_W  512
#define RD_HW (512 * 512)
#define RPT   4

__global__ __launch_bounds__(256, 5) void react_diff_kernel(
    const float* __restrict__ x,
    const float* __restrict__ params,
    float* __restrict__ out)
{
    const float inv_dx2 = 1.0f / (0.06451612903f * 0.06451612903f); // 240.25

    int t    = blockIdx.x * blockDim.x + threadIdx.x; // 0 .. 2^20-1
    int xq   = t & 127;           // float4 group within row
    int tile = (t >> 7) & 127;    // 4-row tile index (512/4 = 128)
    int b    = t >> 14;           // batch
    int lane = threadIdx.x & 31;

    const float* Ubase = x + (size_t)b * 2 * RD_HW;
    const float* Vbase = Ubase + RD_HW;
    float* OU = out + (size_t)b * 2 * RD_HW;
    float* OV = OU + RD_HW;

    float pa = __ldg(&params[b * 3 + 0]);
    float pb = __ldg(&params[b * 3 + 1]);
    float pk = __ldg(&params[b * 3 + 2]);

    int y0 = tile * RPT;
    int x0 = xq << 2;
    int xl = (x0 - 1) & 511;
    int xr = (x0 + 4) & 511;

    #define LDU(y) (((const float4*)(Ubase + (size_t)(y) * RD_W))[xq])
    #define LDV(y) (((const float4*)(Vbase + (size_t)(y) * RD_W))[xq])

    float4 Uu = LDU((y0 - 1) & 511);
    float4 Uc = LDU(y0);
    float4 Vu = LDV((y0 - 1) & 511);
    float4 Vc = LDV(y0);

    #pragma unroll
    for (int r = 0; r < RPT; r++) {
        int y = y0 + r;
        int yd = (y + 1) & 511;
        float4 Ud = LDU(yd);
        float4 Vd = LDV(yd);

        // horizontal neighbors via shuffle; warp-edge lanes load scalar
        float Ul = __shfl_up_sync(0xFFFFFFFFu, Uc.w, 1);
        float Vl = __shfl_up_sync(0xFFFFFFFFu, Vc.w, 1);
        float Ur = __shfl_down_sync(0xFFFFFFFFu, Uc.x, 1);
        float Vr = __shfl_down_sync(0xFFFFFFFFu, Vc.x, 1);
        if (lane == 0) {
            Ul = Ubase[(size_t)y * RD_W + xl];
            Vl = Vbase[(size_t)y * RD_W + xl];
        }
        if (lane == 31) {
            Ur = Ubase[(size_t)y * RD_W + xr];
            Vr = Vbase[(size_t)y * RD_W + xr];
        }

        float4 lapU, lapV;
        lapU.x = (Ul   + Uc.y + Uu.x + Ud.x - 4.0f * Uc.x) * inv_dx2;
        lapU.y = (Uc.x + Uc.z + Uu.y + Ud.y - 4.0f * Uc.y) * inv_dx2;
        lapU.z = (Uc.y + Uc.w + Uu.z + Ud.z - 4.0f * Uc.z) * inv_dx2;
        lapU.w = (Uc.z + Ur   + Uu.w + Ud.w - 4.0f * Uc.w) * inv_dx2;

        lapV.x = (Vl   + Vc.y + Vu.x + Vd.x - 4.0f * Vc.x) * inv_dx2;
        lapV.y = (Vc.x + Vc.z + Vu.y + Vd.y - 4.0f * Vc.y) * inv_dx2;
        lapV.z = (Vc.y + Vc.w + Vu.z + Vd.z - 4.0f * Vc.z) * inv_dx2;
        lapV.w = (Vc.z + Vr   + Vu.w + Vd.w - 4.0f * Vc.w) * inv_dx2;

        float4 dU, dV;
        dU.x = pa * lapU.x + Uc.x - Uc.x * Uc.x * Uc.x - pk - Vc.x;
        dU.y = pa * lapU.y + Uc.y - Uc.y * Uc.y * Uc.y - pk - Vc.y;
        dU.z = pa * lapU.z + Uc.z - Uc.z * Uc.z * Uc.z - pk - Vc.z;
        dU.w = pa * lapU.w + Uc.w - Uc.w * Uc.w * Uc.w - pk - Vc.w;

        dV.x = pb * lapV.x + Uc.x - Vc.x;
        dV.y = pb * lapV.y + Uc.y - Vc.y;
        dV.z = pb * lapV.z + Uc.z - Vc.z;
        dV.w = pb * lapV.w + Uc.w - Vc.w;

        __stcs((float4*)(OU + (size_t)y * RD_W) + xq, dU);
        __stcs((float4*)(OV + (size_t)y * RD_W) + xq, dV);

        // rotate rows
        Uu = Uc; Uc = Ud;
        Vu = Vc; Vc = Vd;
    }
    #undef LDU
    #undef LDV
}

extern "C" void kernel_launch(void* const* d_in, const int* in_sizes, int n_in,
                              void* d_out, int out_size)
{
    const float* x      = (const float*)d_in[1];
    const float* params = (const float*)d_in[2];
    float* out          = (float*)d_out;

    // 64 batches * 128 row-tiles * 128 groups = 2^20 threads
    const int threads = 256;
    const int blocks  = (64 * 128 * 128) / threads; // 4096
    react_diff_kernel<<<blocks, threads>>>(x, params, out);
}